// round 4
// baseline (speedup 1.0000x reference)
#include <cuda_runtime.h>
#include <cuda_bf16.h>
#include <cstdint>

#define HDIM 128
#define MH 64
#define MAXB 2048
#define ROWS_PER_BLOCK 1024
#define ROWS_PER_WARP 128
#define LN_EPS 1e-5f
#define GPB 8   // graphs per MLP block

// ---------------- scratch (static device globals; zero-initialized) -------
// ZERO is the identity for every array:
//   g_sum/g_sq/g_cnt : additive identity
//   g_maxb           : holds max of fkey(v);  fkey(finite) >= 0x00800000 > 0
//   g_minb           : holds max of fkey(-v) (min via negation); same bound
// The MLP kernel zeroes its slice after reading, so graph replays see
// identity state without a separate init kernel.
__device__ float    g_sum [MAXB * HDIM];
__device__ float    g_sq  [MAXB * HDIM];
__device__ unsigned g_minb[MAXB * HDIM];   // max of fkey(-v)
__device__ unsigned g_maxb[MAXB * HDIM];   // max of fkey(v)
__device__ float    g_cnt [MAXB];

// order-preserving float <-> uint key (for atomicMax)
__device__ __forceinline__ unsigned fkey(float f) {
    unsigned b = __float_as_uint(f);
    return (b & 0x80000000u) ? ~b : (b | 0x80000000u);
}
__device__ __forceinline__ float funkey(unsigned k) {
    return __uint_as_float((k & 0x80000000u) ? (k ^ 0x80000000u) : ~k);
}

// ---------------- phase 1: segment reduction, warp-per-row float4 ----------
struct Acc4 {
    float4 s, q, mn, mx;
    int cnt;
};

__device__ __forceinline__ void acc_reset(Acc4& a, const float4& v) {
    a.s = v;
    a.q = make_float4(v.x * v.x, v.y * v.y, v.z * v.z, v.w * v.w);
    a.mn = v;
    a.mx = v;
    a.cnt = 1;
}
__device__ __forceinline__ void acc_add(Acc4& a, const float4& v) {
    a.s.x += v.x; a.s.y += v.y; a.s.z += v.z; a.s.w += v.w;
    a.q.x = fmaf(v.x, v.x, a.q.x);
    a.q.y = fmaf(v.y, v.y, a.q.y);
    a.q.z = fmaf(v.z, v.z, a.q.z);
    a.q.w = fmaf(v.w, v.w, a.q.w);
    a.mn.x = fminf(a.mn.x, v.x); a.mn.y = fminf(a.mn.y, v.y);
    a.mn.z = fminf(a.mn.z, v.z); a.mn.w = fminf(a.mn.w, v.w);
    a.mx.x = fmaxf(a.mx.x, v.x); a.mx.y = fmaxf(a.mx.y, v.y);
    a.mx.z = fmaxf(a.mx.z, v.z); a.mx.w = fmaxf(a.mx.w, v.w);
}

__device__ __forceinline__ void acc_flush(const Acc4& a, int seg, int colbase, int lane) {
    int o = seg * HDIM + colbase;
    atomicAdd(&g_sum[o + 0], a.s.x);
    atomicAdd(&g_sum[o + 1], a.s.y);
    atomicAdd(&g_sum[o + 2], a.s.z);
    atomicAdd(&g_sum[o + 3], a.s.w);
    atomicAdd(&g_sq[o + 0], a.q.x);
    atomicAdd(&g_sq[o + 1], a.q.y);
    atomicAdd(&g_sq[o + 2], a.q.z);
    atomicAdd(&g_sq[o + 3], a.q.w);
    // min via max of negated key (zero-identity)
    atomicMax(&g_minb[o + 0], fkey(-a.mn.x));
    atomicMax(&g_minb[o + 1], fkey(-a.mn.y));
    atomicMax(&g_minb[o + 2], fkey(-a.mn.z));
    atomicMax(&g_minb[o + 3], fkey(-a.mn.w));
    atomicMax(&g_maxb[o + 0], fkey(a.mx.x));
    atomicMax(&g_maxb[o + 1], fkey(a.mx.y));
    atomicMax(&g_maxb[o + 2], fkey(a.mx.z));
    atomicMax(&g_maxb[o + 3], fkey(a.mx.w));
    if (lane == 0) atomicAdd(&g_cnt[seg], (float)a.cnt);
}

__global__ void __launch_bounds__(256) seg_phase1(const float4* __restrict__ x4,
                                                  const int* __restrict__ batch,
                                                  int N) {
    __shared__ int sb[ROWS_PER_BLOCK];
    const int tid = threadIdx.x;
    const int warp = tid >> 5;
    const int lane = tid & 31;
    const long long blockStart = (long long)blockIdx.x * ROWS_PER_BLOCK;
    const int rows = (int)min((long long)ROWS_PER_BLOCK, (long long)N - blockStart);
    if (rows <= 0) return;

    for (int i = tid; i < rows; i += 256) sb[i] = batch[blockStart + i];
    __syncthreads();

    const int wstart = warp * ROWS_PER_WARP;
    if (wstart >= rows) return;
    const int wend = min(wstart + ROWS_PER_WARP, rows);

    const float4* xp = x4 + (blockStart + wstart) * (HDIM / 4) + lane;

    Acc4 a;
    int cur = sb[wstart];
    {
        float4 v0 = __ldcs(xp);
        acc_reset(a, v0);
        xp += HDIM / 4;
    }

    int i = wstart + 1;
    for (; i + 8 <= wend; i += 8) {
        float4 v[8];
#pragma unroll
        for (int j = 0; j < 8; ++j) v[j] = __ldcs(xp + j * (HDIM / 4));
        if (sb[i + 7] == cur) {
#pragma unroll
            for (int j = 0; j < 8; ++j) acc_add(a, v[j]);
            a.cnt += 8;
        } else {
#pragma unroll
            for (int j = 0; j < 8; ++j) {
                int sg = sb[i + j];
                if (sg != cur) {
                    acc_flush(a, cur, lane * 4, lane);
                    cur = sg;
                    acc_reset(a, v[j]);
                } else {
                    acc_add(a, v[j]);
                    a.cnt++;
                }
            }
        }
        xp += 8 * (HDIM / 4);
    }
    for (; i < wend; ++i) {
        float4 v = __ldcs(xp);
        int sg = sb[i];
        if (sg != cur) {
            acc_flush(a, cur, lane * 4, lane);
            cur = sg;
            acc_reset(a, v);
        } else {
            acc_add(a, v);
            a.cnt++;
        }
        xp += HDIM / 4;
    }
    acc_flush(a, cur, lane * 4, lane);
}

// ---------------- phase 2: 8 graphs per block, weights amortized -----------
__global__ void __launch_bounds__(256) mlp_kernel(
    const float* __restrict__ u,
    const float* __restrict__ W0, const float* __restrict__ b0,
    const float* __restrict__ W1, const float* __restrict__ b1,
    const float* __restrict__ W2, const float* __restrict__ b2,
    const float* __restrict__ lng, const float* __restrict__ lnb,
    const float* __restrict__ W3, const float* __restrict__ b3,
    float* __restrict__ out, int B) {
    const int t = threadIdx.x;
    const int gbase = blockIdx.x * GPB;
    const int ng = min(GPB, B - gbase);
    if (ng <= 0) return;

    __shared__ float concat[GPB][5 * HDIM];   // 20 KB
    __shared__ float part[4][GPB][MH];        // 8 KB partials
    __shared__ float hbuf[GPB][MH];
    __shared__ float hln[GPB][MH];
    __shared__ float cnts[GPB];

    if (t < GPB) cnts[t] = (t < ng) ? fmaxf(g_cnt[gbase + t], 1.0f) : 1.0f;
    __syncthreads();

    // build concat = [u, s, min, max, var] for ng graphs
    for (int idx = t; idx < ng * (5 * HDIM); idx += 256) {
        int g = idx / (5 * HDIM);
        int j = idx - g * (5 * HDIM);
        int go = (gbase + g) * HDIM;
        float val;
        int sec = j >> 7;        // 0..4
        int c = j & (HDIM - 1);
        if (sec == 0) {
            val = u[go + c];
        } else if (sec == 1) {
            val = g_sum[go + c];
        } else if (sec == 2) {
            val = -funkey(g_minb[go + c]);       // undo negation
        } else if (sec == 3) {
            val = funkey(g_maxb[go + c]);
        } else {
            float cv = cnts[g];
            float me = g_sum[go + c] / cv;
            val = g_sq[go + c] / cv - me * me;
        }
        concat[g][j] = val;
    }
    __syncthreads();

    const int m = t & 63;        // output feature
    const int q = t >> 6;        // k-split 0..3

    // ---- layer 0: 640 -> 64, K split 4 ways ----
    {
        float acc[GPB];
#pragma unroll
        for (int g = 0; g < GPB; ++g) acc[g] = 0.f;
        const int k0 = q * 160;
#pragma unroll 4
        for (int k = k0; k < k0 + 160; ++k) {
            float w = __ldg(&W0[k * MH + m]);
#pragma unroll
            for (int g = 0; g < GPB; ++g) acc[g] = fmaf(concat[g][k], w, acc[g]);
        }
#pragma unroll
        for (int g = 0; g < GPB; ++g) part[q][g][m] = acc[g];
    }
    __syncthreads();
    for (int idx = t; idx < GPB * MH; idx += 256) {
        int g = idx >> 6, mm = idx & 63;
        hbuf[g][mm] = fmaxf(part[0][g][mm] + part[1][g][mm] + part[2][g][mm] +
                            part[3][g][mm] + b0[mm], 0.f);
    }
    __syncthreads();

    // ---- layer 1: 64 -> 64 ----
    {
        float acc[GPB];
#pragma unroll
        for (int g = 0; g < GPB; ++g) acc[g] = 0.f;
        const int k0 = q * 16;
#pragma unroll
        for (int k = k0; k < k0 + 16; ++k) {
            float w = __ldg(&W1[k * MH + m]);
#pragma unroll
            for (int g = 0; g < GPB; ++g) acc[g] = fmaf(hbuf[g][k], w, acc[g]);
        }
#pragma unroll
        for (int g = 0; g < GPB; ++g) part[q][g][m] = acc[g];
    }
    __syncthreads();
    for (int idx = t; idx < GPB * MH; idx += 256) {
        int g = idx >> 6, mm = idx & 63;
        hln[g][mm] = fmaxf(part[0][g][mm] + part[1][g][mm] + part[2][g][mm] +
                           part[3][g][mm] + b1[mm], 0.f);
    }
    __syncthreads();

    // ---- layer 2: 64 -> 64 ----
    {
        float acc[GPB];
#pragma unroll
        for (int g = 0; g < GPB; ++g) acc[g] = 0.f;
        const int k0 = q * 16;
#pragma unroll
        for (int k = k0; k < k0 + 16; ++k) {
            float w = __ldg(&W2[k * MH + m]);
#pragma unroll
            for (int g = 0; g < GPB; ++g) acc[g] = fmaf(hln[g][k], w, acc[g]);
        }
#pragma unroll
        for (int g = 0; g < GPB; ++g) part[q][g][m] = acc[g];
    }
    __syncthreads();
    for (int idx = t; idx < GPB * MH; idx += 256) {
        int g = idx >> 6, mm = idx & 63;
        hbuf[g][mm] = fmaxf(part[0][g][mm] + part[1][g][mm] + part[2][g][mm] +
                            part[3][g][mm] + b2[mm], 0.f);
    }
    __syncthreads();

    // ---- layernorm: one warp per graph, two-pass over 64 features ----
    {
        int w = t >> 5, lane = t & 31;
        if (w < GPB) {
            float v0 = hbuf[w][lane], v1 = hbuf[w][lane + 32];
            float s = v0 + v1;
#pragma unroll
            for (int o = 16; o > 0; o >>= 1) s += __shfl_xor_sync(0xFFFFFFFF, s, o);
            float mu = s * (1.0f / MH);
            float d0 = v0 - mu, d1 = v1 - mu;
            float vs = d0 * d0 + d1 * d1;
#pragma unroll
            for (int o = 16; o > 0; o >>= 1) vs += __shfl_xor_sync(0xFFFFFFFF, vs, o);
            float rstd = rsqrtf(vs * (1.0f / MH) + LN_EPS);
            hln[w][lane]      = d0 * rstd * lng[lane]      + lnb[lane];
            hln[w][lane + 32] = d1 * rstd * lng[lane + 32] + lnb[lane + 32];
        }
    }
    __syncthreads();

    // ---- output layer: 64 -> 128 + residual; thread = (col, 4-graph slot) ----
    {
        const int col = t & 127;
        const int gs = t >> 7;          // 0 or 1 -> graphs [gs*4, gs*4+4)
        float acc[4] = {0.f, 0.f, 0.f, 0.f};
#pragma unroll 8
        for (int k = 0; k < MH; ++k) {
            float w = __ldg(&W3[k * HDIM + col]);
#pragma unroll
            for (int i = 0; i < 4; ++i) acc[i] = fmaf(hln[gs * 4 + i][k], w, acc[i]);
        }
        float bb = b3[col];
#pragma unroll
        for (int i = 0; i < 4; ++i) {
            int g = gs * 4 + i;
            if (g < ng) {
                int o = (gbase + g) * HDIM + col;
                out[o] = u[o] + bb + acc[i];
            }
        }
    }

    // ---- reset scratch slice to zero-identity for next replay ----
    for (int idx = t; idx < ng * HDIM; idx += 256) {
        int o = gbase * HDIM + idx;
        g_sum[o] = 0.f;
        g_sq[o] = 0.f;
        g_minb[o] = 0u;
        g_maxb[o] = 0u;
    }
    if (t < ng) g_cnt[gbase + t] = 0.f;
}

// ---------------- launch ----------------
extern "C" void kernel_launch(void* const* d_in, const int* in_sizes, int n_in,
                              void* d_out, int out_size) {
    const float* x     = (const float*)d_in[0];
    // d_in[1] edge_index, d_in[2] edge_attr : unused by the forward
    const float* u     = (const float*)d_in[3];
    const int*   batch = (const int*)d_in[4];
    const float* W0    = (const float*)d_in[5];
    const float* b0    = (const float*)d_in[6];
    const float* W1    = (const float*)d_in[7];
    const float* b1    = (const float*)d_in[8];
    const float* W2    = (const float*)d_in[9];
    const float* b2    = (const float*)d_in[10];
    const float* lng   = (const float*)d_in[11];
    const float* lnb   = (const float*)d_in[12];
    const float* W3    = (const float*)d_in[13];
    const float* b3    = (const float*)d_in[14];
    float* out = (float*)d_out;

    const int N = in_sizes[0] / HDIM;
    int B = in_sizes[3] / HDIM;
    if (B > MAXB) B = MAXB;

    const int nBlocks = (N + ROWS_PER_BLOCK - 1) / ROWS_PER_BLOCK;
    seg_phase1<<<nBlocks, 256>>>((const float4*)x, batch, N);

    mlp_kernel<<<(B + GPB - 1) / GPB, 256>>>(u, W0, b0, W1, b1, W2, b2,
                                             lng, lnb, W3, b3, out, B);
}

// round 5
// speedup vs baseline: 1.0196x; 1.0196x over previous
#include <cuda_runtime.h>
#include <cuda_bf16.h>
#include <cstdint>

#define HDIM 128
#define MH 64
#define MAXB 2048
#define ROWS_PER_BLOCK 1024
#define ROWS_PER_WARP 128
#define LN_EPS 1e-5f

// ---------------- scratch (static device globals; zero-initialized) -------
// ZERO is the identity for every array:
//   g_sum/g_sq/g_cnt : additive identity
//   g_maxb           : max of fkey(v);  fkey(finite) >= 0x00800000 > 0
//   g_minb           : max of fkey(-v) (min via negation); same bound
// mlp_kernel zeroes its graph's slice after reading, so every graph replay
// sees identity state without a separate init kernel.
__device__ float    g_sum [MAXB * HDIM];
__device__ float    g_sq  [MAXB * HDIM];
__device__ unsigned g_minb[MAXB * HDIM];   // max of fkey(-v)
__device__ unsigned g_maxb[MAXB * HDIM];   // max of fkey(v)
__device__ float    g_cnt [MAXB];

// order-preserving float <-> uint key (for atomicMax)
__device__ __forceinline__ unsigned fkey(float f) {
    unsigned b = __float_as_uint(f);
    return (b & 0x80000000u) ? ~b : (b | 0x80000000u);
}
__device__ __forceinline__ float funkey(unsigned k) {
    return __uint_as_float((k & 0x80000000u) ? (k ^ 0x80000000u) : ~k);
}

// ---------------- phase 1: segment reduction, warp-per-row float4 ----------
struct Acc4 {
    float4 s, q, mn, mx;
    int cnt;
};

__device__ __forceinline__ void acc_reset(Acc4& a, const float4& v) {
    a.s = v;
    a.q = make_float4(v.x * v.x, v.y * v.y, v.z * v.z, v.w * v.w);
    a.mn = v;
    a.mx = v;
    a.cnt = 1;
}
__device__ __forceinline__ void acc_add(Acc4& a, const float4& v) {
    a.s.x += v.x; a.s.y += v.y; a.s.z += v.z; a.s.w += v.w;
    a.q.x = fmaf(v.x, v.x, a.q.x);
    a.q.y = fmaf(v.y, v.y, a.q.y);
    a.q.z = fmaf(v.z, v.z, a.q.z);
    a.q.w = fmaf(v.w, v.w, a.q.w);
    a.mn.x = fminf(a.mn.x, v.x); a.mn.y = fminf(a.mn.y, v.y);
    a.mn.z = fminf(a.mn.z, v.z); a.mn.w = fminf(a.mn.w, v.w);
    a.mx.x = fmaxf(a.mx.x, v.x); a.mx.y = fmaxf(a.mx.y, v.y);
    a.mx.z = fmaxf(a.mx.z, v.z); a.mx.w = fmaxf(a.mx.w, v.w);
}

__device__ __forceinline__ void acc_flush(const Acc4& a, int seg, int colbase, int lane) {
    int o = seg * HDIM + colbase;
    atomicAdd(&g_sum[o + 0], a.s.x);
    atomicAdd(&g_sum[o + 1], a.s.y);
    atomicAdd(&g_sum[o + 2], a.s.z);
    atomicAdd(&g_sum[o + 3], a.s.w);
    atomicAdd(&g_sq[o + 0], a.q.x);
    atomicAdd(&g_sq[o + 1], a.q.y);
    atomicAdd(&g_sq[o + 2], a.q.z);
    atomicAdd(&g_sq[o + 3], a.q.w);
    // min via max of negated key (zero-identity)
    atomicMax(&g_minb[o + 0], fkey(-a.mn.x));
    atomicMax(&g_minb[o + 1], fkey(-a.mn.y));
    atomicMax(&g_minb[o + 2], fkey(-a.mn.z));
    atomicMax(&g_minb[o + 3], fkey(-a.mn.w));
    atomicMax(&g_maxb[o + 0], fkey(a.mx.x));
    atomicMax(&g_maxb[o + 1], fkey(a.mx.y));
    atomicMax(&g_maxb[o + 2], fkey(a.mx.z));
    atomicMax(&g_maxb[o + 3], fkey(a.mx.w));
    if (lane == 0) atomicAdd(&g_cnt[seg], (float)a.cnt);
}

__global__ void __launch_bounds__(256) seg_phase1(const float4* __restrict__ x4,
                                                  const int* __restrict__ batch,
                                                  int N) {
    __shared__ int sb[ROWS_PER_BLOCK];
    const int tid = threadIdx.x;
    const int warp = tid >> 5;
    const int lane = tid & 31;
    const long long blockStart = (long long)blockIdx.x * ROWS_PER_BLOCK;
    const int rows = (int)min((long long)ROWS_PER_BLOCK, (long long)N - blockStart);
    if (rows <= 0) return;

    for (int i = tid; i < rows; i += 256) sb[i] = batch[blockStart + i];
    __syncthreads();

    const int wstart = warp * ROWS_PER_WARP;
    if (wstart >= rows) return;
    const int wend = min(wstart + ROWS_PER_WARP, rows);

    const float4* xp = x4 + (blockStart + wstart) * (HDIM / 4) + lane;

    Acc4 a;
    int cur = sb[wstart];
    {
        float4 v0 = __ldcs(xp);
        acc_reset(a, v0);
        xp += HDIM / 4;
    }

    int i = wstart + 1;
    for (; i + 8 <= wend; i += 8) {
        float4 v[8];
#pragma unroll
        for (int j = 0; j < 8; ++j) v[j] = __ldcs(xp + j * (HDIM / 4));
        if (sb[i + 7] == cur) {
#pragma unroll
            for (int j = 0; j < 8; ++j) acc_add(a, v[j]);
            a.cnt += 8;
        } else {
#pragma unroll
            for (int j = 0; j < 8; ++j) {
                int sg = sb[i + j];
                if (sg != cur) {
                    acc_flush(a, cur, lane * 4, lane);
                    cur = sg;
                    acc_reset(a, v[j]);
                } else {
                    acc_add(a, v[j]);
                    a.cnt++;
                }
            }
        }
        xp += 8 * (HDIM / 4);
    }
    for (; i < wend; ++i) {
        float4 v = __ldcs(xp);
        int sg = sb[i];
        if (sg != cur) {
            acc_flush(a, cur, lane * 4, lane);
            cur = sg;
            acc_reset(a, v);
        } else {
            acc_add(a, v);
            a.cnt++;
        }
        xp += HDIM / 4;
    }
    acc_flush(a, cur, lane * 4, lane);
}

// ---------------- phase 2: per-graph block (proven fast), self-resetting ----
__global__ void __launch_bounds__(128) mlp_kernel(
    const float* __restrict__ u,
    const float* __restrict__ W0, const float* __restrict__ b0,
    const float* __restrict__ W1, const float* __restrict__ b1,
    const float* __restrict__ W2, const float* __restrict__ b2,
    const float* __restrict__ lng, const float* __restrict__ lnb,
    const float* __restrict__ W3, const float* __restrict__ b3,
    float* __restrict__ out) {
    const int b = blockIdx.x;
    const int t = threadIdx.x;

    __shared__ float concat[5 * HDIM];
    __shared__ float h[MH];
    __shared__ float hn[MH];
    __shared__ float hp[128];
    __shared__ float mu_s, rstd_s;

    // build concat = [u, s, min, max, var]
    {
        float cntv = fmaxf(g_cnt[b], 1.0f);
        int o = b * HDIM + t;
        float sv = g_sum[o];
        float me = sv / cntv;
        concat[t]            = u[o];
        concat[HDIM + t]     = sv;
        concat[2 * HDIM + t] = -funkey(g_minb[o]);   // undo negation
        concat[3 * HDIM + t] = funkey(g_maxb[o]);
        concat[4 * HDIM + t] = g_sq[o] / cntv - me * me;

        // reset this graph's scratch slice to zero-identity for next replay
        g_sum[o] = 0.f;
        g_sq[o] = 0.f;
        g_minb[o] = 0u;
        g_maxb[o] = 0u;
        if (t == 0) g_cnt[b] = 0.f;
    }
    __syncthreads();

    const int m = t & 63;
    const int half = t >> 6;

    // layer 0: 640 -> 64 (split K over two halves)
    {
        float acc = 0.f;
        const float* w = W0 + (size_t)half * 320 * MH + m;
        const float* c = concat + half * 320;
#pragma unroll 8
        for (int k = 0; k < 320; ++k) acc += c[k] * __ldg(&w[k * MH]);
        hp[t] = acc;
    }
    __syncthreads();
    if (t < MH) h[t] = fmaxf(hp[t] + hp[t + 64] + b0[t], 0.f);
    __syncthreads();

    // layer 1: 64 -> 64
    {
        float acc = 0.f;
        const float* w = W1 + (size_t)half * 32 * MH + m;
        const float* c = h + half * 32;
#pragma unroll
        for (int k = 0; k < 32; ++k) acc += c[k] * __ldg(&w[k * MH]);
        hp[t] = acc;
    }
    __syncthreads();
    if (t < MH) hn[t] = fmaxf(hp[t] + hp[t + 64] + b1[t], 0.f);
    __syncthreads();

    // layer 2: 64 -> 64
    {
        float acc = 0.f;
        const float* w = W2 + (size_t)half * 32 * MH + m;
        const float* c = hn + half * 32;
#pragma unroll
        for (int k = 0; k < 32; ++k) acc += c[k] * __ldg(&w[k * MH]);
        hp[t] = acc;
    }
    __syncthreads();
    if (t < MH) h[t] = fmaxf(hp[t] + hp[t + 64] + b2[t], 0.f);
    __syncthreads();

    // layernorm over the 64 features (warp 0, shuffle reduce)
    if (t < 32) {
        float v0 = h[t], v1 = h[t + 32];
        float s = v0 + v1;
#pragma unroll
        for (int o = 16; o > 0; o >>= 1) s += __shfl_xor_sync(0xFFFFFFFF, s, o);
        float mu = s * (1.0f / MH);
        float d0 = v0 - mu, d1 = v1 - mu;
        float vs = d0 * d0 + d1 * d1;
#pragma unroll
        for (int o = 16; o > 0; o >>= 1) vs += __shfl_xor_sync(0xFFFFFFFF, vs, o);
        float rstd = rsqrtf(vs * (1.0f / MH) + LN_EPS);
        hn[t]      = d0 * rstd * lng[t]      + lnb[t];
        hn[t + 32] = d1 * rstd * lng[t + 32] + lnb[t + 32];
    }
    __syncthreads();

    // output layer: 64 -> 128 + residual
    float acc = b3[t];
#pragma unroll 8
    for (int k = 0; k < MH; ++k) acc += hn[k] * __ldg(&W3[k * HDIM + t]);
    out[b * HDIM + t] = u[b * HDIM + t] + acc;
}

// ---------------- launch ----------------
extern "C" void kernel_launch(void* const* d_in, const int* in_sizes, int n_in,
                              void* d_out, int out_size) {
    const float* x     = (const float*)d_in[0];
    // d_in[1] edge_index, d_in[2] edge_attr : unused by the forward
    const float* u     = (const float*)d_in[3];
    const int*   batch = (const int*)d_in[4];
    const float* W0    = (const float*)d_in[5];
    const float* b0    = (const float*)d_in[6];
    const float* W1    = (const float*)d_in[7];
    const float* b1    = (const float*)d_in[8];
    const float* W2    = (const float*)d_in[9];
    const float* b2    = (const float*)d_in[10];
    const float* lng   = (const float*)d_in[11];
    const float* lnb   = (const float*)d_in[12];
    const float* W3    = (const float*)d_in[13];
    const float* b3    = (const float*)d_in[14];
    float* out = (float*)d_out;

    const int N = in_sizes[0] / HDIM;
    int B = in_sizes[3] / HDIM;
    if (B > MAXB) B = MAXB;

    const int nBlocks = (N + ROWS_PER_BLOCK - 1) / ROWS_PER_BLOCK;
    seg_phase1<<<nBlocks, 256>>>((const float4*)x, batch, N);

    mlp_kernel<<<B, 128>>>(u, W0, b0, W1, b1, W2, b2, lng, lnb, W3, b3, out);
}

// round 7
// speedup vs baseline: 1.1074x; 1.0861x over previous
#include <cuda_runtime.h>
#include <cuda_bf16.h>
#include <cstdint>

#define HDIM 128
#define MH 64
#define MAXB 2048
#define ROWS_PER_BLOCK 1024
#define ROWS_PER_WARP 128
#define LN_EPS 1e-5f

// ---------------- scratch (static device globals; zero-initialized) -------
// ZERO is the identity for every array:
//   g_sum/g_sq/g_cnt : additive identity
//   g_maxb           : max of fkey(v);  fkey(finite) >= 0x00800000 > 0
//   g_minb           : max of fkey(-v) (min via negation); same bound
// mlp_kernel zeroes its graph's slice after producing output, so every graph
// replay sees identity state without a separate init kernel.
__device__ float    g_sum [MAXB * HDIM];
__device__ float    g_sq  [MAXB * HDIM];
__device__ unsigned g_minb[MAXB * HDIM];   // max of fkey(-v)
__device__ unsigned g_maxb[MAXB * HDIM];   // max of fkey(v)
__device__ float    g_cnt [MAXB];

// order-preserving float <-> uint key (for atomicMax)
__device__ __forceinline__ unsigned fkey(float f) {
    unsigned b = __float_as_uint(f);
    return (b & 0x80000000u) ? ~b : (b | 0x80000000u);
}
__device__ __forceinline__ float funkey(unsigned k) {
    return __uint_as_float((k & 0x80000000u) ? (k ^ 0x80000000u) : ~k);
}

// ---------------- phase 1: segment reduction, warp-per-row float4 ----------
struct Acc4 {
    float4 s, q, mn, mx;
    int cnt;
};

__device__ __forceinline__ void acc_reset(Acc4& a, const float4& v) {
    a.s = v;
    a.q = make_float4(v.x * v.x, v.y * v.y, v.z * v.z, v.w * v.w);
    a.mn = v;
    a.mx = v;
    a.cnt = 1;
}
__device__ __forceinline__ void acc_add(Acc4& a, const float4& v) {
    a.s.x += v.x; a.s.y += v.y; a.s.z += v.z; a.s.w += v.w;
    a.q.x = fmaf(v.x, v.x, a.q.x);
    a.q.y = fmaf(v.y, v.y, a.q.y);
    a.q.z = fmaf(v.z, v.z, a.q.z);
    a.q.w = fmaf(v.w, v.w, a.q.w);
    a.mn.x = fminf(a.mn.x, v.x); a.mn.y = fminf(a.mn.y, v.y);
    a.mn.z = fminf(a.mn.z, v.z); a.mn.w = fminf(a.mn.w, v.w);
    a.mx.x = fmaxf(a.mx.x, v.x); a.mx.y = fmaxf(a.mx.y, v.y);
    a.mx.z = fmaxf(a.mx.z, v.z); a.mx.w = fmaxf(a.mx.w, v.w);
}

__device__ __forceinline__ void acc_flush(const Acc4& a, int seg, int colbase, int lane) {
    int o = seg * HDIM + colbase;
    atomicAdd(&g_sum[o + 0], a.s.x);
    atomicAdd(&g_sum[o + 1], a.s.y);
    atomicAdd(&g_sum[o + 2], a.s.z);
    atomicAdd(&g_sum[o + 3], a.s.w);
    atomicAdd(&g_sq[o + 0], a.q.x);
    atomicAdd(&g_sq[o + 1], a.q.y);
    atomicAdd(&g_sq[o + 2], a.q.z);
    atomicAdd(&g_sq[o + 3], a.q.w);
    atomicMax(&g_minb[o + 0], fkey(-a.mn.x));
    atomicMax(&g_minb[o + 1], fkey(-a.mn.y));
    atomicMax(&g_minb[o + 2], fkey(-a.mn.z));
    atomicMax(&g_minb[o + 3], fkey(-a.mn.w));
    atomicMax(&g_maxb[o + 0], fkey(a.mx.x));
    atomicMax(&g_maxb[o + 1], fkey(a.mx.y));
    atomicMax(&g_maxb[o + 2], fkey(a.mx.z));
    atomicMax(&g_maxb[o + 3], fkey(a.mx.w));
    if (lane == 0) atomicAdd(&g_cnt[seg], (float)a.cnt);
}

__global__ void __launch_bounds__(256) seg_phase1(const float4* __restrict__ x4,
                                                  const int* __restrict__ batch,
                                                  int N) {
    __shared__ int sb[ROWS_PER_BLOCK];
    const int tid = threadIdx.x;
    const int warp = tid >> 5;
    const int lane = tid & 31;
    const long long blockStart = (long long)blockIdx.x * ROWS_PER_BLOCK;
    const int rows = (int)min((long long)ROWS_PER_BLOCK, (long long)N - blockStart);
    if (rows <= 0) return;

    for (int i = tid; i < rows; i += 256) sb[i] = batch[blockStart + i];
    __syncthreads();

    const int wstart = warp * ROWS_PER_WARP;
    if (wstart >= rows) return;
    const int wend = min(wstart + ROWS_PER_WARP, rows);

    const float4* xp = x4 + (blockStart + wstart) * (HDIM / 4) + lane;

    Acc4 a;
    int cur = sb[wstart];
    {
        float4 v0 = __ldcs(xp);
        acc_reset(a, v0);
        xp += HDIM / 4;
    }

    int i = wstart + 1;
    for (; i + 8 <= wend; i += 8) {
        float4 v[8];
#pragma unroll
        for (int j = 0; j < 8; ++j) v[j] = __ldcs(xp + j * (HDIM / 4));
        if (sb[i + 7] == cur) {
#pragma unroll
            for (int j = 0; j < 8; ++j) acc_add(a, v[j]);
            a.cnt += 8;
        } else {
#pragma unroll
            for (int j = 0; j < 8; ++j) {
                int sg = sb[i + j];
                if (sg != cur) {
                    acc_flush(a, cur, lane * 4, lane);
                    cur = sg;
                    acc_reset(a, v[j]);
                } else {
                    acc_add(a, v[j]);
                    a.cnt++;
                }
            }
        }
        xp += 8 * (HDIM / 4);
    }
    for (; i < wend; ++i) {
        float4 v = __ldcs(xp);
        int sg = sb[i];
        if (sg != cur) {
            acc_flush(a, cur, lane * 4, lane);
            cur = sg;
            acc_reset(a, v);
        } else {
            acc_add(a, v);
            a.cnt++;
        }
        xp += HDIM / 4;
    }
    acc_flush(a, cur, lane * 4, lane);
}

// ---------------- phase 2: per-graph block, 256 threads, wide loads --------
__global__ void __launch_bounds__(256) mlp_kernel(
    const float* __restrict__ u,
    const float* __restrict__ W0, const float* __restrict__ b0,
    const float* __restrict__ W1, const float* __restrict__ b1,
    const float* __restrict__ W2, const float* __restrict__ b2,
    const float* __restrict__ lng, const float* __restrict__ lnb,
    const float* __restrict__ W3, const float* __restrict__ b3,
    float* __restrict__ out) {
    const int b = blockIdx.x;
    const int t = threadIdx.x;

    __shared__ float concat[5 * HDIM];
    __shared__ float part0[16][MH + 1];   // padded stride 65: conflict-free
    __shared__ float part1[4][MH + 1];
    __shared__ float part3[2][HDIM];
    __shared__ float h0[MH];
    __shared__ float hb[MH];

    // ---- build concat = [u, s, min, max, var] ----
    if (t < HDIM) {
        float cntv = fmaxf(g_cnt[b], 1.0f);
        int o = b * HDIM + t;
        float sv = g_sum[o];
        float me = sv / cntv;
        concat[t]            = u[o];
        concat[HDIM + t]     = sv;
        concat[2 * HDIM + t] = -funkey(g_minb[o]);   // undo negation
        concat[3 * HDIM + t] = funkey(g_maxb[o]);
        concat[4 * HDIM + t] = g_sq[o] / cntv - me * me;
    }
    __syncthreads();

    // ---- layer 0: 640 -> 64; 16-way K-split, 4 outputs/thread via float4 ----
    {
        const int mg = (t & 15) * 4;     // output group base
        const int q  = t >> 4;           // k-slice 0..15
        float a0 = 0.f, a1 = 0.f, a2 = 0.f, a3 = 0.f;
        const int k0 = q * 40;
#pragma unroll 8
        for (int k = k0; k < k0 + 40; ++k) {
            float c = concat[k];
            float4 w = *(const float4*)&W0[k * MH + mg];
            a0 = fmaf(c, w.x, a0);
            a1 = fmaf(c, w.y, a1);
            a2 = fmaf(c, w.z, a2);
            a3 = fmaf(c, w.w, a3);
        }
        part0[q][mg + 0] = a0;
        part0[q][mg + 1] = a1;
        part0[q][mg + 2] = a2;
        part0[q][mg + 3] = a3;
    }
    __syncthreads();
    if (t < MH) {
        float s = 0.f;
#pragma unroll
        for (int q = 0; q < 16; ++q) s += part0[q][t];
        h0[t] = fmaxf(s + b0[t], 0.f);
    }
    __syncthreads();

    // ---- layer 1: 64 -> 64; 4-way K-split ----
    {
        const int m = t & 63;
        const int q = t >> 6;
        float acc = 0.f;
        const int k0 = q * 16;
#pragma unroll
        for (int k = k0; k < k0 + 16; ++k)
            acc = fmaf(h0[k], __ldg(&W1[k * MH + m]), acc);
        part1[q][m] = acc;
    }
    __syncthreads();
    if (t < MH)
        hb[t] = fmaxf(part1[0][t] + part1[1][t] + part1[2][t] + part1[3][t] + b1[t], 0.f);
    __syncthreads();

    // ---- layer 2: 64 -> 64; 4-way K-split ----
    {
        const int m = t & 63;
        const int q = t >> 6;
        float acc = 0.f;
        const int k0 = q * 16;
#pragma unroll
        for (int k = k0; k < k0 + 16; ++k)
            acc = fmaf(hb[k], __ldg(&W2[k * MH + m]), acc);
        part1[q][m] = acc;
    }
    __syncthreads();
    if (t < MH)
        h0[t] = fmaxf(part1[0][t] + part1[1][t] + part1[2][t] + part1[3][t] + b2[t], 0.f);
    __syncthreads();

    // ---- layernorm over 64 features (warp 0, shuffle reduce) ----
    if (t < 32) {
        float v0 = h0[t], v1 = h0[t + 32];
        float s = v0 + v1;
#pragma unroll
        for (int o = 16; o > 0; o >>= 1) s += __shfl_xor_sync(0xFFFFFFFF, s, o);
        float mu = s * (1.0f / MH);
        float d0 = v0 - mu, d1 = v1 - mu;
        float vs = d0 * d0 + d1 * d1;
#pragma unroll
        for (int o = 16; o > 0; o >>= 1) vs += __shfl_xor_sync(0xFFFFFFFF, vs, o);
        float rstd = rsqrtf(vs * (1.0f / MH) + LN_EPS);
        hb[t]      = d0 * rstd * lng[t]      + lnb[t];
        hb[t + 32] = d1 * rstd * lng[t + 32] + lnb[t + 32];
    }
    __syncthreads();

    // ---- output layer: 64 -> 128 + residual; 2-way K-split ----
    {
        const int col = t & 127;
        const int hf  = t >> 7;
        float acc = 0.f;
        const int k0 = hf * 32;
#pragma unroll 8
        for (int k = k0; k < k0 + 32; ++k)
            acc = fmaf(hb[k], __ldg(&W3[k * HDIM + col]), acc);
        part3[hf][col] = acc;
    }
    __syncthreads();
    if (t < HDIM) {
        int o = b * HDIM + t;
        out[o] = u[o] + b3[t] + part3[0][t] + part3[1][t];
    }

    // ---- reset scratch slice to zero-identity for next replay ----
    {
        int c = t & 127;
        int o = b * HDIM + c;
        if (t < 128) {
            g_sum[o] = 0.f;
            g_sq[o] = 0.f;
        } else {
            g_minb[o] = 0u;
            g_maxb[o] = 0u;
        }
        if (t == 0) g_cnt[b] = 0.f;
    }
}

// ---------------- launch ----------------
extern "C" void kernel_launch(void* const* d_in, const int* in_sizes, int n_in,
                              void* d_out, int out_size) {
    const float* x     = (const float*)d_in[0];
    // d_in[1] edge_index, d_in[2] edge_attr : unused by the forward
    const float* u     = (const float*)d_in[3];
    const int*   batch = (const int*)d_in[4];
    const float* W0    = (const float*)d_in[5];
    const float* b0    = (const float*)d_in[6];
    const float* W1    = (const float*)d_in[7];
    const float* b1    = (const float*)d_in[8];
    const float* W2    = (const float*)d_in[9];
    const float* b2    = (const float*)d_in[10];
    const float* lng   = (const float*)d_in[11];
    const float* lnb   = (const float*)d_in[12];
    const float* W3    = (const float*)d_in[13];
    const float* b3    = (const float*)d_in[14];
    float* out = (float*)d_out;

    const int N = in_sizes[0] / HDIM;
    int B = in_sizes[3] / HDIM;
    if (B > MAXB) B = MAXB;

    const int nBlocks = (N + ROWS_PER_BLOCK - 1) / ROWS_PER_BLOCK;
    seg_phase1<<<nBlocks, 256>>>((const float4*)x, batch, N);

    mlp_kernel<<<B, 256>>>(u, W0, b0, W1, b1, W2, b2, lng, lnb, W3, b3, out);
}